// round 13
// baseline (speedup 1.0000x reference)
#include <cuda_runtime.h>
#include <cuda_bf16.h>
#include <cstdint>

// ---------------------------------------------------------------------------
// LorentzLayer: out[b,a] = sum_{c,d} G[c][d][a] * T[b,c,d]
// Round 13: HYBRID TMA + LDG. LDG path caps at ~5.8 TB/s (L1tex outstanding
// sectors) and TMA path at ~6.1 TB/s (TMA/LTS service) — two different
// per-SM path caps. Run both concurrently: warps 0-7 consume TMA-staged
// 16-row tiles (rows [0, 131072), R11 pipeline, producer = tid0,
// arrive-after-compute — the config that measured best); warps 8-15 stream
// rows [131072, 262144) via the R9 register path (LDG __ldcs). If DRAM has
// headroom the two caps add; if not, this lands at R11 parity.
// ---------------------------------------------------------------------------

#define NCLUSTER   100
#define BATCH_N    262144
#define NBLOCKS    148
#define THREADS    512
#define NW_TMA     8                           // TMA consumer warps (0-7)
#define NW_LDG     8                           // LDG warps (8-15)
#define TILE_ROWS  16
#define ROW_BYTES  1600                        // 400 floats
#define TILE_BYTES (TILE_ROWS * ROW_BYTES)     // 25600
#define HALF_ROWS  (BATCH_N / 2)               // 131072
#define NTILES     (HALF_ROWS / TILE_ROWS)     // 8192 TMA tiles
#define STAGES     4
#define LDG_WARPS  (NBLOCKS * NW_LDG)          // 1184
#define LDG_UNITS  (HALF_ROWS / 2)             // 65536 two-row units

// ---------------- mbarrier / bulk-copy primitives ----------------

__device__ __forceinline__ uint32_t s2u(const void* p) {
    return (uint32_t)__cvta_generic_to_shared(p);
}
__device__ __forceinline__ void mbar_init(uint32_t a, uint32_t cnt) {
    asm volatile("mbarrier.init.shared.b64 [%0], %1;" :: "r"(a), "r"(cnt) : "memory");
}
__device__ __forceinline__ void mbar_expect_tx(uint32_t a, uint32_t bytes) {
    asm volatile("mbarrier.arrive.expect_tx.shared.b64 _, [%0], %1;"
                 :: "r"(a), "r"(bytes) : "memory");
}
__device__ __forceinline__ void mbar_arrive(uint32_t a) {
    asm volatile("mbarrier.arrive.shared.b64 _, [%0];" :: "r"(a) : "memory");
}
__device__ __forceinline__ void mbar_wait(uint32_t a, uint32_t ph) {
    asm volatile(
        "{\n\t.reg .pred p;\n"
        "WL%=:\n\t"
        "mbarrier.try_wait.parity.shared.b64 p, [%0], %1;\n\t"
        "@!p bra WL%=;\n\t}"
        :: "r"(a), "r"(ph) : "memory");
}
__device__ __forceinline__ void bulk_g2s(uint32_t dst, const void* src,
                                         uint32_t bytes, uint32_t mbar) {
    asm volatile(
        "cp.async.bulk.shared::cta.global.mbarrier::complete_tx::bytes "
        "[%0], [%1], %2, [%3];"
        :: "r"(dst), "l"((uint64_t)__cvta_generic_to_global(src)),
           "r"(bytes), "r"(mbar) : "memory");
}

// ---------------- closed-form G construction ----------------

__device__ __forceinline__ void build_boost(float B[4][4],
                                            float b0, float b1, float b2) {
    float mag2 = b0 * b0 + b1 * b1 + b2 * b2;
    float g = 1.0f / sqrtf(1.0f - mag2);
    float inv_mag2 = 1.0f / mag2;
    float gm1 = g - 1.0f;

    B[0][0] = g;
    B[0][1] = -g * b0; B[0][2] = -g * b1; B[0][3] = -g * b2;
    B[1][0] = -g * b0; B[2][0] = -g * b1; B[3][0] = -g * b2;

    float bb[3] = {b0, b1, b2};
    #pragma unroll
    for (int i = 0; i < 3; i++) {
        #pragma unroll
        for (int j = 0; j < 3; j++) {
            float v = gm1 * bb[i] * bb[j] * inv_mag2;
            if (i == j) v += 1.0f;
            B[i + 1][j + 1] = v;
        }
    }
}

// Gd[d].{x,y,z,w} = (Bim @ (w * Bc))[a=0..3][d]
__device__ __forceinline__ void make_G(const float Bim[4][4],
                                       const float* __restrict__ Bo,
                                       float w, int c, float4 Gd[4]) {
    float Bc[4][4];
    build_boost(Bc, Bo[3 * c + 0], Bo[3 * c + 1], Bo[3 * c + 2]);
    #pragma unroll
    for (int d = 0; d < 4; d++) {
        float s0 = 0.f, s1 = 0.f, s2 = 0.f, s3 = 0.f;
        #pragma unroll
        for (int m = 0; m < 4; m++) {
            s0 += Bim[0][m] * Bc[m][d];
            s1 += Bim[1][m] * Bc[m][d];
            s2 += Bim[2][m] * Bc[m][d];
            s3 += Bim[3][m] * Bc[m][d];
        }
        Gd[d] = make_float4(s0 * w, s1 * w, s2 * w, s3 * w);
    }
}

#define ACCUM4(v0, v1, G)                                               \
    do {                                                                \
        ax0 += v0.x * G[0].x + v0.y * G[1].x + v0.z * G[2].x + v0.w * G[3].x; \
        ay0 += v0.x * G[0].y + v0.y * G[1].y + v0.z * G[2].y + v0.w * G[3].y; \
        az0 += v0.x * G[0].z + v0.y * G[1].z + v0.z * G[2].z + v0.w * G[3].z; \
        aw0 += v0.x * G[0].w + v0.y * G[1].w + v0.z * G[2].w + v0.w * G[3].w; \
        ax1 += v1.x * G[0].x + v1.y * G[1].x + v1.z * G[2].x + v1.w * G[3].x; \
        ay1 += v1.x * G[0].y + v1.y * G[1].y + v1.z * G[2].y + v1.w * G[3].y; \
        az1 += v1.x * G[0].z + v1.y * G[1].z + v1.z * G[2].z + v1.w * G[3].z; \
        aw1 += v1.x * G[0].w + v1.y * G[1].w + v1.z * G[2].w + v1.w * G[3].w; \
    } while (0)

// Component-folding butterfly (verified R8-R12): every lane ends with the
// full-warp sum of component (lane&3). 9 shuffles per 4-vector.
__device__ __forceinline__ float reduce_vec4(float ax, float ay, float az,
                                             float aw, int lane) {
    const unsigned F = 0xffffffffu;
    float sx = ax + __shfl_xor_sync(F, ax, 1);
    float sy = ay + __shfl_xor_sync(F, ay, 1);
    float sz = az + __shfl_xor_sync(F, az, 1);
    float sw = aw + __shfl_xor_sync(F, aw, 1);
    float p = (lane & 1) ? sy : sx;
    float q = (lane & 1) ? sw : sz;
    p += __shfl_xor_sync(F, p, 2);
    q += __shfl_xor_sync(F, q, 2);
    float r = (lane & 2) ? q : p;
    r += __shfl_xor_sync(F, r, 4);
    r += __shfl_xor_sync(F, r, 8);
    r += __shfl_xor_sync(F, r, 16);
    return r;   // lane l holds component (l&3)
}

// ---------------- main kernel ----------------

__global__ __launch_bounds__(THREADS, 1)
void lorentz_main_kernel(const float* __restrict__ T,
                         const float* __restrict__ Bo,
                         const float* __restrict__ Bi,
                         const float* __restrict__ W,
                         float* __restrict__ out) {
    extern __shared__ __align__(128) char dsm[];   // STAGES * TILE_BYTES
    __shared__ float4 gtail[4][4];
    __shared__ __align__(8) uint64_t mbars[2 * STAGES];  // full[s], empty[STAGES+s]

    int tid  = threadIdx.x;
    int lane = tid & 31;
    int warp = tid >> 5;
    int bid  = blockIdx.x;

    // --- register-resident G (all warps need it) ---
    float Bim[4][4];
    build_boost(Bim, Bi[0], Bi[1], Bi[2]);

    float4 G0[4], G1[4], G2[4], GT[4];
    make_G(Bim, Bo, W[lane],      lane,      G0);
    make_G(Bim, Bo, W[32 + lane], 32 + lane, G1);
    make_G(Bim, Bo, W[64 + lane], 64 + lane, G2);

    if (tid < 4) {
        float4 gt[4];
        make_G(Bim, Bo, W[96 + tid], 96 + tid, gt);
        gtail[tid][0] = gt[0];
        gtail[tid][1] = gt[1];
        gtail[tid][2] = gt[2];
        gtail[tid][3] = gt[3];
    }
    if (tid == 0) {
        #pragma unroll
        for (int s = 0; s < STAGES; s++) {
            mbar_init(s2u(&mbars[s]), 1);               // full: producer
            mbar_init(s2u(&mbars[STAGES + s]), NW_TMA); // empty: 8 warps
        }
    }
    __syncthreads();

    GT[0] = gtail[lane & 3][0];
    GT[1] = gtail[lane & 3][1];
    GT[2] = gtail[lane & 3][2];
    GT[3] = gtail[lane & 3][3];

    const float4 ZERO = make_float4(0.f, 0.f, 0.f, 0.f);

    if (warp < NW_TMA) {
        // ============ TMA half: rows [0, HALF_ROWS) ============
        int mytiles = (NTILES - bid + NBLOCKS - 1) / NBLOCKS;

        if (tid == 0) {   // producer prologue (R11 style)
            int npro = mytiles < STAGES ? mytiles : STAGES;
            for (int p = 0; p < npro; p++) {
                uint32_t fb = s2u(&mbars[p]);
                mbar_expect_tx(fb, TILE_BYTES);
                bulk_g2s(s2u(dsm) + p * TILE_BYTES,
                         T + (size_t)(bid + p * NBLOCKS) * TILE_ROWS * 400,
                         TILE_BYTES, fb);
            }
        }

        for (int k = 0; k < mytiles; k++) {
            int s = k % STAGES;
            uint32_t ph = (uint32_t)((k / STAGES) & 1);
            uint32_t fb = s2u(&mbars[s]);
            uint32_t eb = s2u(&mbars[STAGES + s]);

            mbar_wait(fb, ph);

            const char* SB = dsm + s * TILE_BYTES;
            const float4* t0 = (const float4*)(SB + warp * 2 * ROW_BYTES);
            const float4* t1 = t0 + 100;

            float4 v00 = t0[lane];
            float4 v01 = t0[32 + lane];
            float4 v02 = t0[64 + lane];
            float4 v10 = t1[lane];
            float4 v11 = t1[32 + lane];
            float4 v12 = t1[64 + lane];
            float4 vt0 = ZERO, vt1 = ZERO;
            if (lane < 4) {
                vt0 = t0[96 + lane];
                vt1 = t1[96 + lane];
            }

            float ax0 = 0.f, ay0 = 0.f, az0 = 0.f, aw0 = 0.f;
            float ax1 = 0.f, ay1 = 0.f, az1 = 0.f, aw1 = 0.f;
            ACCUM4(v00, v10, G0);
            ACCUM4(v01, v11, G1);
            ACCUM4(v02, v12, G2);
            ACCUM4(vt0, vt1, GT);

            float r0 = reduce_vec4(ax0, ay0, az0, aw0, lane);
            float r1 = reduce_vec4(ax1, ay1, az1, aw1, lane);

            int grow = (bid + k * NBLOCKS) * TILE_ROWS + warp * 2;
            if (lane < 4) {
                out[(size_t)grow * 4 + lane]     = r0;
                out[(size_t)grow * 4 + 4 + lane] = r1;
            }

            __syncwarp();
            if (lane == 0) mbar_arrive(eb);

            if (tid == 0 && k + STAGES < mytiles) {
                mbar_wait(eb, ph);
                mbar_expect_tx(fb, TILE_BYTES);
                bulk_g2s(s2u(dsm) + s * TILE_BYTES,
                         T + (size_t)(bid + (k + STAGES) * NBLOCKS) * TILE_ROWS * 400,
                         TILE_BYTES, fb);
            }
        }
    } else {
        // ============ LDG half: rows [HALF_ROWS, BATCH_N) ============
        int wid = bid * NW_LDG + (warp - NW_TMA);

        for (int u = wid; u < LDG_UNITS; u += LDG_WARPS) {
            size_t row0 = (size_t)HALF_ROWS + (size_t)u * 2;
            const float4* t0 = (const float4*)T + row0 * 100;
            const float4* t1 = t0 + 100;

            float4 v00 = __ldcs(t0 + lane);
            float4 v01 = __ldcs(t0 + 32 + lane);
            float4 v02 = __ldcs(t0 + 64 + lane);
            float4 v10 = __ldcs(t1 + lane);
            float4 v11 = __ldcs(t1 + 32 + lane);
            float4 v12 = __ldcs(t1 + 64 + lane);
            float4 vt0 = ZERO, vt1 = ZERO;
            if (lane < 4) {
                vt0 = __ldcs(t0 + 96 + lane);
                vt1 = __ldcs(t1 + 96 + lane);
            }

            float ax0 = 0.f, ay0 = 0.f, az0 = 0.f, aw0 = 0.f;
            float ax1 = 0.f, ay1 = 0.f, az1 = 0.f, aw1 = 0.f;
            ACCUM4(v00, v10, G0);
            ACCUM4(v01, v11, G1);
            ACCUM4(v02, v12, G2);
            ACCUM4(vt0, vt1, GT);

            float r0 = reduce_vec4(ax0, ay0, az0, aw0, lane);
            float r1 = reduce_vec4(ax1, ay1, az1, aw1, lane);

            if (lane < 4) {
                out[row0 * 4 + lane]     = r0;
                out[row0 * 4 + 4 + lane] = r1;
            }
        }
    }
}

extern "C" void kernel_launch(void* const* d_in, const int* in_sizes, int n_in,
                              void* d_out, int out_size) {
    const float* T  = (const float*)d_in[0];   // (262144, 100, 4)
    const float* Bo = (const float*)d_in[1];   // (100, 3)
    const float* Bi = (const float*)d_in[2];   // (1, 3)
    const float* W  = (const float*)d_in[3];   // (100, 1)
    // d_in[4] = K_mats — encoded analytically in build_boost.

    float* out = (float*)d_out;                // (262144, 1, 4)

    static bool attr_set = false;
    if (!attr_set) {   // idempotent attribute config (not a graph/stream op)
        cudaFuncSetAttribute(lorentz_main_kernel,
                             cudaFuncAttributeMaxDynamicSharedMemorySize,
                             STAGES * TILE_BYTES);
        attr_set = true;
    }

    lorentz_main_kernel<<<NBLOCKS, THREADS, STAGES * TILE_BYTES>>>(
        T, Bo, Bi, W, out);
}

// round 14
// speedup vs baseline: 1.1106x; 1.1106x over previous
#include <cuda_runtime.h>
#include <cuda_bf16.h>
#include <cstdint>

// ---------------------------------------------------------------------------
// LorentzLayer: out[b,a] = sum_{c,d} G[c][d][a] * T[b,c,d]
// Round 14: R11 (best measured: 69.7us, 6.15 TB/s) with two cadence fixes:
//   (1) STAGES 3 -> 4 (204.8 KB smem) — absorbs producer refill-gating on
//       its own warp's compute tail;
//   (2) each tile filled by 2 x 25.6 KB bulk copies on the same mbarrier —
//       doubles in-flight TMA queue entries per SM.
// Producer = tid0, arrive-after-compute (R12 proved the alternatives regress).
// Compute: 16 warps x 2 rows/tile, register-resident G, butterfly reduction.
// ---------------------------------------------------------------------------

#define NCLUSTER   100
#define BATCH_N    262144
#define NBLOCKS    148
#define THREADS    512
#define NWARP      16
#define TILE_ROWS  32
#define ROW_BYTES  1600                       // 400 floats
#define TILE_BYTES (TILE_ROWS * ROW_BYTES)    // 51200
#define HALF_TILE  (TILE_BYTES / 2)           // 25600
#define NTILES     (BATCH_N / TILE_ROWS)      // 8192
#define STAGES     4

// ---------------- mbarrier / bulk-copy primitives ----------------

__device__ __forceinline__ uint32_t s2u(const void* p) {
    return (uint32_t)__cvta_generic_to_shared(p);
}
__device__ __forceinline__ void mbar_init(uint32_t a, uint32_t cnt) {
    asm volatile("mbarrier.init.shared.b64 [%0], %1;" :: "r"(a), "r"(cnt) : "memory");
}
__device__ __forceinline__ void mbar_expect_tx(uint32_t a, uint32_t bytes) {
    asm volatile("mbarrier.arrive.expect_tx.shared.b64 _, [%0], %1;"
                 :: "r"(a), "r"(bytes) : "memory");
}
__device__ __forceinline__ void mbar_arrive(uint32_t a) {
    asm volatile("mbarrier.arrive.shared.b64 _, [%0];" :: "r"(a) : "memory");
}
__device__ __forceinline__ void mbar_wait(uint32_t a, uint32_t ph) {
    asm volatile(
        "{\n\t.reg .pred p;\n"
        "WL%=:\n\t"
        "mbarrier.try_wait.parity.shared.b64 p, [%0], %1;\n\t"
        "@!p bra WL%=;\n\t}"
        :: "r"(a), "r"(ph) : "memory");
}
__device__ __forceinline__ void bulk_g2s(uint32_t dst, const void* src,
                                         uint32_t bytes, uint32_t mbar) {
    asm volatile(
        "cp.async.bulk.shared::cta.global.mbarrier::complete_tx::bytes "
        "[%0], [%1], %2, [%3];"
        :: "r"(dst), "l"((uint64_t)__cvta_generic_to_global(src)),
           "r"(bytes), "r"(mbar) : "memory");
}

// Fill one stage with tile k: expect full tile bytes, issue 2 half-tile copies.
#define FILL_STAGE(stage, tileidx)                                          \
    do {                                                                    \
        uint32_t _fb = s2u(&mbars[stage]);                                  \
        mbar_expect_tx(_fb, TILE_BYTES);                                    \
        const float* _src = T + (size_t)(bid + (tileidx) * NBLOCKS)         \
                                  * TILE_ROWS * 400;                        \
        uint32_t _d = s2u(dsm) + (stage) * TILE_BYTES;                      \
        bulk_g2s(_d, _src, HALF_TILE, _fb);                                 \
        bulk_g2s(_d + HALF_TILE, (const char*)_src + HALF_TILE,             \
                 HALF_TILE, _fb);                                           \
    } while (0)

// ---------------- closed-form G construction ----------------

__device__ __forceinline__ void build_boost(float B[4][4],
                                            float b0, float b1, float b2) {
    float mag2 = b0 * b0 + b1 * b1 + b2 * b2;
    float g = 1.0f / sqrtf(1.0f - mag2);
    float inv_mag2 = 1.0f / mag2;
    float gm1 = g - 1.0f;

    B[0][0] = g;
    B[0][1] = -g * b0; B[0][2] = -g * b1; B[0][3] = -g * b2;
    B[1][0] = -g * b0; B[2][0] = -g * b1; B[3][0] = -g * b2;

    float bb[3] = {b0, b1, b2};
    #pragma unroll
    for (int i = 0; i < 3; i++) {
        #pragma unroll
        for (int j = 0; j < 3; j++) {
            float v = gm1 * bb[i] * bb[j] * inv_mag2;
            if (i == j) v += 1.0f;
            B[i + 1][j + 1] = v;
        }
    }
}

// Gd[d].{x,y,z,w} = (Bim @ (w * Bc))[a=0..3][d]
__device__ __forceinline__ void make_G(const float Bim[4][4],
                                       const float* __restrict__ Bo,
                                       float w, int c, float4 Gd[4]) {
    float Bc[4][4];
    build_boost(Bc, Bo[3 * c + 0], Bo[3 * c + 1], Bo[3 * c + 2]);
    #pragma unroll
    for (int d = 0; d < 4; d++) {
        float s0 = 0.f, s1 = 0.f, s2 = 0.f, s3 = 0.f;
        #pragma unroll
        for (int m = 0; m < 4; m++) {
            s0 += Bim[0][m] * Bc[m][d];
            s1 += Bim[1][m] * Bc[m][d];
            s2 += Bim[2][m] * Bc[m][d];
            s3 += Bim[3][m] * Bc[m][d];
        }
        Gd[d] = make_float4(s0 * w, s1 * w, s2 * w, s3 * w);
    }
}

#define ACCUM4(v0, v1, G)                                               \
    do {                                                                \
        ax0 += v0.x * G[0].x + v0.y * G[1].x + v0.z * G[2].x + v0.w * G[3].x; \
        ay0 += v0.x * G[0].y + v0.y * G[1].y + v0.z * G[2].y + v0.w * G[3].y; \
        az0 += v0.x * G[0].z + v0.y * G[1].z + v0.z * G[2].z + v0.w * G[3].z; \
        aw0 += v0.x * G[0].w + v0.y * G[1].w + v0.z * G[2].w + v0.w * G[3].w; \
        ax1 += v1.x * G[0].x + v1.y * G[1].x + v1.z * G[2].x + v1.w * G[3].x; \
        ay1 += v1.x * G[0].y + v1.y * G[1].y + v1.z * G[2].y + v1.w * G[3].y; \
        az1 += v1.x * G[0].z + v1.y * G[1].z + v1.z * G[2].z + v1.w * G[3].z; \
        aw1 += v1.x * G[0].w + v1.y * G[1].w + v1.z * G[2].w + v1.w * G[3].w; \
    } while (0)

// Component-folding butterfly (verified R8-R13): every lane ends with the
// full-warp sum of component (lane&3). 9 shuffles per 4-vector.
__device__ __forceinline__ float reduce_vec4(float ax, float ay, float az,
                                             float aw, int lane) {
    const unsigned F = 0xffffffffu;
    float sx = ax + __shfl_xor_sync(F, ax, 1);
    float sy = ay + __shfl_xor_sync(F, ay, 1);
    float sz = az + __shfl_xor_sync(F, az, 1);
    float sw = aw + __shfl_xor_sync(F, aw, 1);
    float p = (lane & 1) ? sy : sx;
    float q = (lane & 1) ? sw : sz;
    p += __shfl_xor_sync(F, p, 2);
    q += __shfl_xor_sync(F, q, 2);
    float r = (lane & 2) ? q : p;
    r += __shfl_xor_sync(F, r, 4);
    r += __shfl_xor_sync(F, r, 8);
    r += __shfl_xor_sync(F, r, 16);
    return r;   // lane l holds component (l&3)
}

// ---------------- main kernel ----------------

__global__ __launch_bounds__(THREADS, 1)
void lorentz_main_kernel(const float* __restrict__ T,
                         const float* __restrict__ Bo,
                         const float* __restrict__ Bi,
                         const float* __restrict__ W,
                         float* __restrict__ out) {
    extern __shared__ __align__(128) char dsm[];   // STAGES * TILE_BYTES
    __shared__ float4 gtail[4][4];
    __shared__ __align__(8) uint64_t mbars[2 * STAGES];  // full[s], empty[STAGES+s]

    int tid  = threadIdx.x;
    int lane = tid & 31;
    int warp = tid >> 5;
    int bid  = blockIdx.x;

    // --- register-resident G prologue (R9 design) ---
    float Bim[4][4];
    build_boost(Bim, Bi[0], Bi[1], Bi[2]);

    float4 G0[4], G1[4], G2[4], GT[4];
    make_G(Bim, Bo, W[lane],      lane,      G0);
    make_G(Bim, Bo, W[32 + lane], 32 + lane, G1);
    make_G(Bim, Bo, W[64 + lane], 64 + lane, G2);

    if (tid < 4) {
        float4 gt[4];
        make_G(Bim, Bo, W[96 + tid], 96 + tid, gt);
        gtail[tid][0] = gt[0];
        gtail[tid][1] = gt[1];
        gtail[tid][2] = gt[2];
        gtail[tid][3] = gt[3];
    }

    if (tid == 0) {
        #pragma unroll
        for (int s = 0; s < STAGES; s++) {
            mbar_init(s2u(&mbars[s]), 1);               // full: producer
            mbar_init(s2u(&mbars[STAGES + s]), NWARP);  // empty: 16 warps
        }
    }
    __syncthreads();

    GT[0] = gtail[lane & 3][0];
    GT[1] = gtail[lane & 3][1];
    GT[2] = gtail[lane & 3][2];
    GT[3] = gtail[lane & 3][3];

    // tiles for this block: bid, bid+148, ...
    int mytiles = (NTILES - bid + NBLOCKS - 1) / NBLOCKS;

    // --- producer prologue: fill up to STAGES stages ---
    if (tid == 0) {
        int npro = mytiles < STAGES ? mytiles : STAGES;
        for (int p = 0; p < npro; p++) FILL_STAGE(p, p);
    }

    const float4 ZERO = make_float4(0.f, 0.f, 0.f, 0.f);

    for (int k = 0; k < mytiles; k++) {
        int s = k % STAGES;
        uint32_t ph = (uint32_t)((k / STAGES) & 1);
        uint32_t fb = s2u(&mbars[s]);
        uint32_t eb = s2u(&mbars[STAGES + s]);

        mbar_wait(fb, ph);   // tile k resident in stage s

        const char* SB = dsm + s * TILE_BYTES;
        const float4* t0 = (const float4*)(SB + warp * 2 * ROW_BYTES);
        const float4* t1 = t0 + 100;

        float4 v00 = t0[lane];
        float4 v01 = t0[32 + lane];
        float4 v02 = t0[64 + lane];
        float4 v10 = t1[lane];
        float4 v11 = t1[32 + lane];
        float4 v12 = t1[64 + lane];
        float4 vt0 = ZERO, vt1 = ZERO;
        if (lane < 4) {
            vt0 = t0[96 + lane];
            vt1 = t1[96 + lane];
        }

        float ax0 = 0.f, ay0 = 0.f, az0 = 0.f, aw0 = 0.f;
        float ax1 = 0.f, ay1 = 0.f, az1 = 0.f, aw1 = 0.f;
        ACCUM4(v00, v10, G0);
        ACCUM4(v01, v11, G1);
        ACCUM4(v02, v12, G2);
        ACCUM4(vt0, vt1, GT);

        float r0 = reduce_vec4(ax0, ay0, az0, aw0, lane);
        float r1 = reduce_vec4(ax1, ay1, az1, aw1, lane);

        int grow = (bid + k * NBLOCKS) * TILE_ROWS + warp * 2;
        if (lane < 4) {
            out[(size_t)grow * 4 + lane]     = r0;
            out[(size_t)grow * 4 + 4 + lane] = r1;
        }

        __syncwarp();
        if (lane == 0) mbar_arrive(eb);   // this warp done with stage s

        // producer: refill stage s with tile k+STAGES once fully drained
        if (tid == 0 && k + STAGES < mytiles) {
            mbar_wait(eb, ph);
            FILL_STAGE(s, k + STAGES);
        }
    }
}

extern "C" void kernel_launch(void* const* d_in, const int* in_sizes, int n_in,
                              void* d_out, int out_size) {
    const float* T  = (const float*)d_in[0];   // (262144, 100, 4)
    const float* Bo = (const float*)d_in[1];   // (100, 3)
    const float* Bi = (const float*)d_in[2];   // (1, 3)
    const float* W  = (const float*)d_in[3];   // (100, 1)
    // d_in[4] = K_mats — encoded analytically in build_boost.

    float* out = (float*)d_out;                // (262144, 1, 4)

    static bool attr_set = false;
    if (!attr_set) {   // idempotent attribute config (not a graph/stream op)
        cudaFuncSetAttribute(lorentz_main_kernel,
                             cudaFuncAttributeMaxDynamicSharedMemorySize,
                             STAGES * TILE_BYTES);
        attr_set = true;
    }

    lorentz_main_kernel<<<NBLOCKS, THREADS, STAGES * TILE_BYTES>>>(
        T, Bo, Bi, W, out);
}

// round 16
// speedup vs baseline: 1.1621x; 1.0463x over previous
#include <cuda_runtime.h>
#include <cuda_bf16.h>
#include <cstdint>

// ---------------------------------------------------------------------------
// LorentzLayer: out[b,a] = sum_{c,d} G[c][d][a] * T[b,c,d]
// Round 16 (resubmit of R15 after broker-side container failure):
// R11 (best: 69.7us / 6.15 TB/s) + ONE change: dedicated producer warp
// (warp 16). R11's producer (tid0 of compute warp 0) serialized each refill
// behind warp-0 compute + full-stage drain (~500 cyc/tile on the critical
// path). R12 bundled this fix with early-release + 4 stages and regressed;
// the ingredients are being tested in isolation.
// Everything else is byte-for-byte R11: 3 stages x 51.2KB whole-tile bulk
// copies, consumers arrive-empty AFTER compute, 16 compute warps x 2 rows,
// register-resident G, component-folding butterfly reduction.
// ---------------------------------------------------------------------------

#define NCLUSTER   100
#define BATCH_N    262144
#define NBLOCKS    148
#define NWARP      16                          // compute warps
#define THREADS    ((NWARP + 1) * 32)          // 544: +1 producer warp
#define TILE_ROWS  32
#define ROW_BYTES  1600                        // 400 floats
#define TILE_BYTES (TILE_ROWS * ROW_BYTES)     // 51200
#define NTILES     (BATCH_N / TILE_ROWS)       // 8192
#define STAGES     3

// ---------------- mbarrier / bulk-copy primitives ----------------

__device__ __forceinline__ uint32_t s2u(const void* p) {
    return (uint32_t)__cvta_generic_to_shared(p);
}
__device__ __forceinline__ void mbar_init(uint32_t a, uint32_t cnt) {
    asm volatile("mbarrier.init.shared.b64 [%0], %1;" :: "r"(a), "r"(cnt) : "memory");
}
__device__ __forceinline__ void mbar_expect_tx(uint32_t a, uint32_t bytes) {
    asm volatile("mbarrier.arrive.expect_tx.shared.b64 _, [%0], %1;"
                 :: "r"(a), "r"(bytes) : "memory");
}
__device__ __forceinline__ void mbar_arrive(uint32_t a) {
    asm volatile("mbarrier.arrive.shared.b64 _, [%0];" :: "r"(a) : "memory");
}
__device__ __forceinline__ void mbar_wait(uint32_t a, uint32_t ph) {
    asm volatile(
        "{\n\t.reg .pred p;\n"
        "WL%=:\n\t"
        "mbarrier.try_wait.parity.shared.b64 p, [%0], %1;\n\t"
        "@!p bra WL%=;\n\t}"
        :: "r"(a), "r"(ph) : "memory");
}
__device__ __forceinline__ void bulk_g2s(uint32_t dst, const void* src,
                                         uint32_t bytes, uint32_t mbar) {
    asm volatile(
        "cp.async.bulk.shared::cta.global.mbarrier::complete_tx::bytes "
        "[%0], [%1], %2, [%3];"
        :: "r"(dst), "l"((uint64_t)__cvta_generic_to_global(src)),
           "r"(bytes), "r"(mbar) : "memory");
}

// ---------------- closed-form G construction ----------------

__device__ __forceinline__ void build_boost(float B[4][4],
                                            float b0, float b1, float b2) {
    float mag2 = b0 * b0 + b1 * b1 + b2 * b2;
    float g = 1.0f / sqrtf(1.0f - mag2);
    float inv_mag2 = 1.0f / mag2;
    float gm1 = g - 1.0f;

    B[0][0] = g;
    B[0][1] = -g * b0; B[0][2] = -g * b1; B[0][3] = -g * b2;
    B[1][0] = -g * b0; B[2][0] = -g * b1; B[3][0] = -g * b2;

    float bb[3] = {b0, b1, b2};
    #pragma unroll
    for (int i = 0; i < 3; i++) {
        #pragma unroll
        for (int j = 0; j < 3; j++) {
            float v = gm1 * bb[i] * bb[j] * inv_mag2;
            if (i == j) v += 1.0f;
            B[i + 1][j + 1] = v;
        }
    }
}

// Gd[d].{x,y,z,w} = (Bim @ (w * Bc))[a=0..3][d]
__device__ __forceinline__ void make_G(const float Bim[4][4],
                                       const float* __restrict__ Bo,
                                       float w, int c, float4 Gd[4]) {
    float Bc[4][4];
    build_boost(Bc, Bo[3 * c + 0], Bo[3 * c + 1], Bo[3 * c + 2]);
    #pragma unroll
    for (int d = 0; d < 4; d++) {
        float s0 = 0.f, s1 = 0.f, s2 = 0.f, s3 = 0.f;
        #pragma unroll
        for (int m = 0; m < 4; m++) {
            s0 += Bim[0][m] * Bc[m][d];
            s1 += Bim[1][m] * Bc[m][d];
            s2 += Bim[2][m] * Bc[m][d];
            s3 += Bim[3][m] * Bc[m][d];
        }
        Gd[d] = make_float4(s0 * w, s1 * w, s2 * w, s3 * w);
    }
}

#define ACCUM4(v0, v1, G)                                               \
    do {                                                                \
        ax0 += v0.x * G[0].x + v0.y * G[1].x + v0.z * G[2].x + v0.w * G[3].x; \
        ay0 += v0.x * G[0].y + v0.y * G[1].y + v0.z * G[2].y + v0.w * G[3].y; \
        az0 += v0.x * G[0].z + v0.y * G[1].z + v0.z * G[2].z + v0.w * G[3].z; \
        aw0 += v0.x * G[0].w + v0.y * G[1].w + v0.z * G[2].w + v0.w * G[3].w; \
        ax1 += v1.x * G[0].x + v1.y * G[1].x + v1.z * G[2].x + v1.w * G[3].x; \
        ay1 += v1.x * G[0].y + v1.y * G[1].y + v1.z * G[2].y + v1.w * G[3].y; \
        az1 += v1.x * G[0].z + v1.y * G[1].z + v1.z * G[2].z + v1.w * G[3].z; \
        aw1 += v1.x * G[0].w + v1.y * G[1].w + v1.z * G[2].w + v1.w * G[3].w; \
    } while (0)

// Component-folding butterfly (verified R8-R14): every lane ends with the
// full-warp sum of component (lane&3). 9 shuffles per 4-vector.
__device__ __forceinline__ float reduce_vec4(float ax, float ay, float az,
                                             float aw, int lane) {
    const unsigned F = 0xffffffffu;
    float sx = ax + __shfl_xor_sync(F, ax, 1);
    float sy = ay + __shfl_xor_sync(F, ay, 1);
    float sz = az + __shfl_xor_sync(F, az, 1);
    float sw = aw + __shfl_xor_sync(F, aw, 1);
    float p = (lane & 1) ? sy : sx;
    float q = (lane & 1) ? sw : sz;
    p += __shfl_xor_sync(F, p, 2);
    q += __shfl_xor_sync(F, q, 2);
    float r = (lane & 2) ? q : p;
    r += __shfl_xor_sync(F, r, 4);
    r += __shfl_xor_sync(F, r, 8);
    r += __shfl_xor_sync(F, r, 16);
    return r;   // lane l holds component (l&3)
}

// ---------------- main kernel ----------------

__global__ __launch_bounds__(THREADS, 1)
void lorentz_main_kernel(const float* __restrict__ T,
                         const float* __restrict__ Bo,
                         const float* __restrict__ Bi,
                         const float* __restrict__ W,
                         float* __restrict__ out) {
    extern __shared__ __align__(128) char dsm[];   // STAGES * TILE_BYTES
    __shared__ float4 gtail[4][4];
    __shared__ __align__(8) uint64_t mbars[2 * STAGES];  // full[s], empty[STAGES+s]

    int tid  = threadIdx.x;
    int lane = tid & 31;
    int warp = tid >> 5;
    int bid  = blockIdx.x;

    if (tid == 0) {
        #pragma unroll
        for (int s = 0; s < STAGES; s++) {
            mbar_init(s2u(&mbars[s]), 1);               // full: producer
            mbar_init(s2u(&mbars[STAGES + s]), NWARP);  // empty: 16 warps
        }
    }

    // tiles for this block: bid, bid+148, ... (contiguous 32-row chunks)
    int mytiles = (NTILES - bid + NBLOCKS - 1) / NBLOCKS;

    // --- register-resident G (compute warps only) ---
    float4 G0[4], G1[4], G2[4], GT[4];
    if (warp < NWARP) {
        float Bim[4][4];
        build_boost(Bim, Bi[0], Bi[1], Bi[2]);
        make_G(Bim, Bo, W[lane],      lane,      G0);
        make_G(Bim, Bo, W[32 + lane], 32 + lane, G1);
        make_G(Bim, Bo, W[64 + lane], 64 + lane, G2);
        if (tid < 4) {
            float4 gt[4];
            make_G(Bim, Bo, W[96 + tid], 96 + tid, gt);
            gtail[tid][0] = gt[0];
            gtail[tid][1] = gt[1];
            gtail[tid][2] = gt[2];
            gtail[tid][3] = gt[3];
        }
    }
    __syncthreads();   // mbars initialized + gtail visible

    if (warp == NWARP) {
        // ---------------- dedicated producer warp ----------------
        if (lane == 0) {
            int npro = mytiles < STAGES ? mytiles : STAGES;
            for (int p = 0; p < npro; p++) {
                uint32_t fb = s2u(&mbars[p]);
                mbar_expect_tx(fb, TILE_BYTES);
                bulk_g2s(s2u(dsm) + p * TILE_BYTES,
                         T + (size_t)(bid + p * NBLOCKS) * TILE_ROWS * 400,
                         TILE_BYTES, fb);
            }
            for (int k = STAGES; k < mytiles; k++) {
                int s = k % STAGES;
                uint32_t jp = (uint32_t)((k / STAGES - 1) & 1);
                mbar_wait(s2u(&mbars[STAGES + s]), jp);   // stage drained
                uint32_t fb = s2u(&mbars[s]);
                mbar_expect_tx(fb, TILE_BYTES);
                bulk_g2s(s2u(dsm) + s * TILE_BYTES,
                         T + (size_t)(bid + k * NBLOCKS) * TILE_ROWS * 400,
                         TILE_BYTES, fb);
            }
        }
        return;
    }

    // ---------------- consumer warps (exact R11 body) ----------------
    GT[0] = gtail[lane & 3][0];
    GT[1] = gtail[lane & 3][1];
    GT[2] = gtail[lane & 3][2];
    GT[3] = gtail[lane & 3][3];

    const float4 ZERO = make_float4(0.f, 0.f, 0.f, 0.f);

    for (int k = 0; k < mytiles; k++) {
        int s = k % STAGES;
        uint32_t ph = (uint32_t)((k / STAGES) & 1);

        mbar_wait(s2u(&mbars[s]), ph);   // tile k resident in stage s

        const char* SB = dsm + s * TILE_BYTES;
        const float4* t0 = (const float4*)(SB + warp * 2 * ROW_BYTES);
        const float4* t1 = t0 + 100;

        float4 v00 = t0[lane];
        float4 v01 = t0[32 + lane];
        float4 v02 = t0[64 + lane];
        float4 v10 = t1[lane];
        float4 v11 = t1[32 + lane];
        float4 v12 = t1[64 + lane];
        float4 vt0 = ZERO, vt1 = ZERO;
        if (lane < 4) {
            vt0 = t0[96 + lane];
            vt1 = t1[96 + lane];
        }

        float ax0 = 0.f, ay0 = 0.f, az0 = 0.f, aw0 = 0.f;
        float ax1 = 0.f, ay1 = 0.f, az1 = 0.f, aw1 = 0.f;
        ACCUM4(v00, v10, G0);
        ACCUM4(v01, v11, G1);
        ACCUM4(v02, v12, G2);
        ACCUM4(vt0, vt1, GT);

        float r0 = reduce_vec4(ax0, ay0, az0, aw0, lane);
        float r1 = reduce_vec4(ax1, ay1, az1, aw1, lane);

        int grow = (bid + k * NBLOCKS) * TILE_ROWS + warp * 2;
        if (lane < 4) {
            out[(size_t)grow * 4 + lane]     = r0;
            out[(size_t)grow * 4 + 4 + lane] = r1;
        }

        __syncwarp();
        if (lane == 0) mbar_arrive(s2u(&mbars[STAGES + s]));
    }
}

extern "C" void kernel_launch(void* const* d_in, const int* in_sizes, int n_in,
                              void* d_out, int out_size) {
    const float* T  = (const float*)d_in[0];   // (262144, 100, 4)
    const float* Bo = (const float*)d_in[1];   // (100, 3)
    const float* Bi = (const float*)d_in[2];   // (1, 3)
    const float* W  = (const float*)d_in[3];   // (100, 1)
    // d_in[4] = K_mats — encoded analytically in build_boost.

    float* out = (float*)d_out;                // (262144, 1, 4)

    static bool attr_set = false;
    if (!attr_set) {   // idempotent attribute config (not a graph/stream op)
        cudaFuncSetAttribute(lorentz_main_kernel,
                             cudaFuncAttributeMaxDynamicSharedMemorySize,
                             STAGES * TILE_BYTES);
        attr_set = true;
    }

    lorentz_main_kernel<<<NBLOCKS, THREADS, STAGES * TILE_BYTES>>>(
        T, Bo, Bi, W, out);
}